// round 1
// baseline (speedup 1.0000x reference)
#include <cuda_runtime.h>

#define Ssz  1024
#define Hh   16
#define Dd   128
#define NBb  64
#define CBSs 32
#define KK   4
#define SBLK 32

// scratch (no cudaMalloc allowed)
__device__ float g_ksum_t[Hh * Dd * NBb];   // [h][d][n], 512 KB
__device__ int   g_topidx[Ssz * Hh * KK];   // 256 KB

// ---------------------------------------------------------------------------
// K1: ksum[n,h,d] = sum_c k_compressed[n,h,c,d], stored transposed per head as
// [h][d][n] so K2 can do conflict-free scalar LDS over n.
// ---------------------------------------------------------------------------
__global__ void ksum_kernel(const float* __restrict__ kc) {
    int b = blockIdx.x;            // n*H + h
    int d = threadIdx.x;           // 0..127
    int n = b >> 4;
    int h = b & (Hh - 1);
    const float* base = kc + (size_t)b * (CBSs * Dd);
    float acc = 0.f;
#pragma unroll
    for (int c = 0; c < CBSs; ++c) acc += base[c * Dd + d];
    g_ksum_t[(h * Dd + d) * NBb + n] = acc;
}

// ---------------------------------------------------------------------------
// K2: block scores + top-4. One CTA = 32 s-values x one head.
//   smem: ksh [d][n] 32KB + qsh [s][d] 16KB (reused as score buffer) = 48KB.
//   Thread tile 2s x 4n, scalar LDS all conflict-free / broadcast.
//   Top-4 matches jax.lax.top_k: descending, strict > (lowest index on tie).
// ---------------------------------------------------------------------------
__global__ __launch_bounds__(256) void score_topk_kernel(const float* __restrict__ q) {
    __shared__ float ksh[Dd * NBb];    // 32768 B
    __shared__ float qsh[SBLK * Dd];   // 16384 B (total 49152 = static max)

    const int h  = blockIdx.y;
    const int s0 = blockIdx.x * SBLK;
    const int tid = threadIdx.x;

    for (int i = tid; i < Dd * NBb; i += 256)
        ksh[i] = g_ksum_t[h * (Dd * NBb) + i];
    for (int i = tid; i < SBLK * Dd; i += 256) {
        int sl = i >> 7, d = i & (Dd - 1);
        qsh[i] = q[((size_t)(s0 + sl) * Hh + h) * Dd + d];
    }
    __syncthreads();

    const int ts = tid >> 4;        // 0..15 -> s rows {ts, ts+16}
    const int tn = tid & 15;        // 0..15 -> n cols {tn, tn+16, tn+32, tn+48}

    float acc[2][4];
#pragma unroll
    for (int i = 0; i < 2; ++i)
#pragma unroll
        for (int j = 0; j < 4; ++j) acc[i][j] = 0.f;

#pragma unroll 4
    for (int d = 0; d < Dd; ++d) {
        float k0 = ksh[d * NBb + tn];
        float k1 = ksh[d * NBb + tn + 16];
        float k2 = ksh[d * NBb + tn + 32];
        float k3 = ksh[d * NBb + tn + 48];
        float q0 = qsh[ts * Dd + d];
        float q1 = qsh[(ts + 16) * Dd + d];
        acc[0][0] += q0 * k0; acc[0][1] += q0 * k1;
        acc[0][2] += q0 * k2; acc[0][3] += q0 * k3;
        acc[1][0] += q1 * k0; acc[1][1] += q1 * k1;
        acc[1][2] += q1 * k2; acc[1][3] += q1 * k3;
    }
    __syncthreads();

    float* sc = qsh;   // reuse as scores [SBLK][65] (padded: conflict-free scans)
#pragma unroll
    for (int i = 0; i < 2; ++i)
#pragma unroll
        for (int j = 0; j < 4; ++j)
            sc[(ts + 16 * i) * 65 + (tn + 16 * j)] = acc[i][j];
    __syncthreads();

    if (tid < SBLK) {
        const float* row = sc + tid * 65;
        unsigned long long mask = 0ull;
        int outbase = ((s0 + tid) * Hh + h) * KK;
#pragma unroll
        for (int p = 0; p < KK; ++p) {
            float bv = -3.402823466e38f;
            int bi = 0;
            for (int n = 0; n < NBb; ++n) {
                if ((mask >> n) & 1ull) continue;
                float v = row[n];
                if (v > bv) { bv = v; bi = n; }   // strict >: lowest index wins ties
            }
            mask |= 1ull << bi;
            g_topidx[outbase + p] = bi;
        }
    }
}

// ---------------------------------------------------------------------------
// K3: gather. One CTA per (s,h,j): copy one 16KB K block and one 16KB V block.
// Src stays L2-resident (32MB, ~128x reuse); dst written with streaming stores.
// ---------------------------------------------------------------------------
__global__ __launch_bounds__(256) void gather_kernel(const float* __restrict__ kc,
                                                     const float* __restrict__ vc,
                                                     float* __restrict__ out) {
    const int b = blockIdx.x;                   // (s*H + h)*4 + j
    const int h = (b >> 2) & (Hh - 1);
    const int n = g_topidx[b];

    const size_t blk4 = (size_t)(CBSs * Dd / 4);          // 1024 float4
    const float4* sk = (const float4*)kc + (size_t)(n * Hh + h) * blk4;
    const float4* sv = (const float4*)vc + (size_t)(n * Hh + h) * blk4;
    float4* dk = (float4*)out + (size_t)b * blk4;
    float4* dv = dk + (size_t)(Ssz * Hh * KK) * blk4;     // V half of output

    const int tid = threadIdx.x;
#pragma unroll
    for (int i = 0; i < 4; ++i) {
        int idx = tid + i * 256;
        float4 a = sk[idx];
        float4 c = sv[idx];
        __stcs(dk + idx, a);
        __stcs(dv + idx, c);
    }
}

extern "C" void kernel_launch(void* const* d_in, const int* in_sizes, int n_in,
                              void* d_out, int out_size) {
    const float* q  = (const float*)d_in[0];
    const float* kc = (const float*)d_in[1];
    const float* vc = (const float*)d_in[2];
    float* out = (float*)d_out;

    ksum_kernel<<<NBb * Hh, Dd>>>(kc);
    score_topk_kernel<<<dim3(Ssz / SBLK, Hh), 256>>>(q);
    gather_kernel<<<Ssz * Hh * KK, 256>>>(kc, vc, out);
}

// round 5
// speedup vs baseline: 1.0025x; 1.0025x over previous
#include <cuda_runtime.h>

#define Ssz  1024
#define Hh   16
#define Dd   128
#define NBb  64
#define CBSs 32
#define KK   4
#define SBLK 32

#define NPICK   (Ssz * Hh * KK)        // 65536
#define NSRC    (NBb * Hh)             // 1024
#define CAPSRC  4096                   // max picks per src (all s of one head)
#define CHUNK   32                     // dests per gather CTA
#define MAXCHUNKS 3072                 // sum ceil(c/32) <= 1024 + 65536/32

// scratch (no cudaMalloc allowed)
__device__ float g_ksum_t[Hh * Dd * NBb];     // [h][d][n]
__device__ int   g_topidx[NPICK];
__device__ int   g_cnt[NSRC];
__device__ int   g_lists[NSRC * CAPSRC];      // 16 MB worst case
__device__ int2  g_chunks[MAXCHUNKS];
__device__ int   g_nchunks;

// ---------------------------------------------------------------------------
// K0: zero per-replay state
// ---------------------------------------------------------------------------
__global__ void zero_kernel() {
    g_cnt[threadIdx.x] = 0;
    if (threadIdx.x == 0) g_nchunks = 0;
}

// ---------------------------------------------------------------------------
// K1: ksum[n,h,d] = sum_c k_compressed[n,h,c,d], stored transposed as [h][d][n]
// ---------------------------------------------------------------------------
__global__ void ksum_kernel(const float* __restrict__ kc) {
    int b = blockIdx.x;            // n*H + h
    int d = threadIdx.x;
    int n = b >> 4;
    int h = b & (Hh - 1);
    const float* base = kc + (size_t)b * (CBSs * Dd);
    float acc = 0.f;
#pragma unroll
    for (int c = 0; c < CBSs; ++c) acc += base[c * Dd + d];
    g_ksum_t[(h * Dd + d) * NBb + n] = acc;
}

// ---------------------------------------------------------------------------
// K2: block scores + top-4 (jax.lax.top_k semantics: strict >, low index wins)
// ---------------------------------------------------------------------------
__global__ __launch_bounds__(256) void score_topk_kernel(const float* __restrict__ q) {
    __shared__ float ksh[Dd * NBb];    // 32 KB
    __shared__ float qsh[SBLK * Dd];   // 16 KB (reused for scores)

    const int h  = blockIdx.y;
    const int s0 = blockIdx.x * SBLK;
    const int tid = threadIdx.x;

    for (int i = tid; i < Dd * NBb; i += 256)
        ksh[i] = g_ksum_t[h * (Dd * NBb) + i];
    for (int i = tid; i < SBLK * Dd; i += 256) {
        int sl = i >> 7, d = i & (Dd - 1);
        qsh[i] = q[((size_t)(s0 + sl) * Hh + h) * Dd + d];
    }
    __syncthreads();

    const int ts = tid >> 4;
    const int tn = tid & 15;

    float acc[2][4];
#pragma unroll
    for (int i = 0; i < 2; ++i)
#pragma unroll
        for (int j = 0; j < 4; ++j) acc[i][j] = 0.f;

#pragma unroll 4
    for (int d = 0; d < Dd; ++d) {
        float k0 = ksh[d * NBb + tn];
        float k1 = ksh[d * NBb + tn + 16];
        float k2 = ksh[d * NBb + tn + 32];
        float k3 = ksh[d * NBb + tn + 48];
        float q0 = qsh[ts * Dd + d];
        float q1 = qsh[(ts + 16) * Dd + d];
        acc[0][0] += q0 * k0; acc[0][1] += q0 * k1;
        acc[0][2] += q0 * k2; acc[0][3] += q0 * k3;
        acc[1][0] += q1 * k0; acc[1][1] += q1 * k1;
        acc[1][2] += q1 * k2; acc[1][3] += q1 * k3;
    }
    __syncthreads();

    float* sc = qsh;   // scores [SBLK][65]
#pragma unroll
    for (int i = 0; i < 2; ++i)
#pragma unroll
        for (int j = 0; j < 4; ++j)
            sc[(ts + 16 * i) * 65 + (tn + 16 * j)] = acc[i][j];
    __syncthreads();

    if (tid < SBLK) {
        const float* row = sc + tid * 65;
        unsigned long long mask = 0ull;
        int outbase = ((s0 + tid) * Hh + h) * KK;
#pragma unroll
        for (int p = 0; p < KK; ++p) {
            float bv = -3.402823466e38f;
            int bi = 0;
            for (int n = 0; n < NBb; ++n) {
                if ((mask >> n) & 1ull) continue;
                float v = row[n];
                if (v > bv) { bv = v; bi = n; }
            }
            mask |= 1ull << bi;
            g_topidx[outbase + p] = bi;
        }
    }
}

// ---------------------------------------------------------------------------
// K3: bucket picks by source block (n*H + h). List order is nondeterministic
// but output doesn't depend on it (each dest written exactly once).
// ---------------------------------------------------------------------------
__global__ __launch_bounds__(1024) void bucket_kernel() {
    int i = blockIdx.x * 1024 + threadIdx.x;      // pick id = (s*H+h)*4 + j
    int n = g_topidx[i];
    int h = (i >> 2) & (Hh - 1);
    int src = n * Hh + h;
    int pos = atomicAdd(&g_cnt[src], 1);
    g_lists[src * CAPSRC + pos] = i;
}

// ---------------------------------------------------------------------------
// K4: split buckets into chunks of <= CHUNK dests for load balance
// ---------------------------------------------------------------------------
__global__ void chunk_kernel() {
    int src = blockIdx.x * 256 + threadIdx.x;
    if (src >= NSRC) return;
    int c = g_cnt[src];
    if (c == 0) return;
    int nch = (c + CHUNK - 1) / CHUNK;
    int base = atomicAdd(&g_nchunks, nch);
    for (int k = 0; k < nch; ++k)
        g_chunks[base + k] = make_int2(src, k * CHUNK);
}

// ---------------------------------------------------------------------------
// K5: gather. One CTA per chunk: load 16KB K + 16KB V src block into registers
// ONCE, replay to up to CHUNK destinations with streaming stores.
// ---------------------------------------------------------------------------
__global__ __launch_bounds__(256) void gather_kernel(const float* __restrict__ kc,
                                                     const float* __restrict__ vc,
                                                     float* __restrict__ out) {
    if ((int)blockIdx.x >= g_nchunks) return;
    int2 ch = g_chunks[blockIdx.x];
    const int src = ch.x;
    const int start = ch.y;
    const int cnt = g_cnt[src];
    const int end = min(start + CHUNK, cnt);

    const size_t blk4 = (size_t)(CBSs * Dd / 4);          // 1024 float4
    const float4* sk = (const float4*)kc + (size_t)src * blk4;
    const float4* sv = (const float4*)vc + (size_t)src * blk4;
    const int tid = threadIdx.x;

    float4 rk[4], rv[4];
#pragma unroll
    for (int i = 0; i < 4; ++i) {
        rk[i] = sk[tid + i * 256];
        rv[i] = sv[tid + i * 256];
    }

    for (int t = start; t < end; ++t) {
        int dest = g_lists[src * CAPSRC + t];
        float4* dk = (float4*)out + (size_t)dest * blk4;
        float4* dv = dk + (size_t)NPICK * blk4;
#pragma unroll
        for (int i = 0; i < 4; ++i) {
            __stcs(dk + tid + i * 256, rk[i]);
            __stcs(dv + tid + i * 256, rv[i]);
        }
    }
}

extern "C" void kernel_launch(void* const* d_in, const int* in_sizes, int n_in,
                              void* d_out, int out_size) {
    const float* q  = (const float*)d_in[0];
    const float* kc = (const float*)d_in[1];
    const float* vc = (const float*)d_in[2];
    float* out = (float*)d_out;

    zero_kernel<<<1, NSRC>>>();
    ksum_kernel<<<NBb * Hh, Dd>>>(kc);
    score_topk_kernel<<<dim3(Ssz / SBLK, Hh), 256>>>(q);
    bucket_kernel<<<NPICK / 1024, 1024>>>();
    chunk_kernel<<<(NSRC + 255) / 256, 256>>>();
    gather_kernel<<<MAXCHUNKS, 256>>>(kc, vc, out);
}

// round 6
// speedup vs baseline: 1.0296x; 1.0270x over previous
#include <cuda_runtime.h>

#define Ssz  1024
#define Hh   16
#define Dd   128
#define NBb  64
#define CBSs 32
#define KK   4
#define SBLK 32

#define NPICK   (Ssz * Hh * KK)        // 65536
#define NSRC    (NBb * Hh)             // 1024
#define CAPSRC  1024                   // max picks per src: 4 picks per (s,h) are distinct n
#define CHUNK   32                     // dests per gather CTA
#define MAXCHUNKS 3072                 // 1024 + 65536/32

// scratch (no cudaMalloc allowed)
__device__ float g_ksum_t[Hh * Dd * NBb];     // [h][d][n]
__device__ int   g_cnt[NSRC];
__device__ int   g_lists[NSRC * CAPSRC];      // 4 MB
__device__ int2  g_chunks[MAXCHUNKS];
__device__ int   g_nchunks;

// ---------------------------------------------------------------------------
// K1: ksum[n,h,d] = sum_c kc[n,h,c,d] -> g_ksum_t[h][d][n], float4 loads.
// Also zeroes per-replay state (grid == NSRC, one counter per block).
// ---------------------------------------------------------------------------
__global__ __launch_bounds__(128) void ksum_kernel(const float* __restrict__ kc) {
    const int b   = blockIdx.x;          // n*H + h
    const int tid = threadIdx.x;         // 0..127
    if (tid == 0) {
        g_cnt[b] = 0;
        if (b == 0) g_nchunks = 0;
    }

    // thread (g, d4): g = tid>>5 sums 8 c-rows, d4 = tid&31 picks float4 column
    const int d4 = tid & 31, g = tid >> 5;
    const float4* base = (const float4*)(kc + (size_t)b * (CBSs * Dd));
    float4 acc = make_float4(0.f, 0.f, 0.f, 0.f);
#pragma unroll
    for (int c = 0; c < 8; ++c) {
        float4 v = base[(size_t)(g * 8 + c) * 32 + d4];
        acc.x += v.x; acc.y += v.y; acc.z += v.z; acc.w += v.w;
    }

    __shared__ float4 sh[128];
    sh[tid] = acc;
    __syncthreads();

    if (tid < 32) {
        float4 a = sh[tid], p = sh[tid + 32], q2 = sh[tid + 64], r = sh[tid + 96];
        a.x += p.x + q2.x + r.x;
        a.y += p.y + q2.y + r.y;
        a.z += p.z + q2.z + r.z;
        a.w += p.w + q2.w + r.w;
        const int n = b >> 4, h = b & (Hh - 1);
        const int d0 = tid * 4;
        g_ksum_t[(h * Dd + d0 + 0) * NBb + n] = a.x;
        g_ksum_t[(h * Dd + d0 + 1) * NBb + n] = a.y;
        g_ksum_t[(h * Dd + d0 + 2) * NBb + n] = a.z;
        g_ksum_t[(h * Dd + d0 + 3) * NBb + n] = a.w;
    }
}

// ---------------------------------------------------------------------------
// K2: block scores + top-4 (jax.lax.top_k: strict >, lowest index wins ties)
// with INLINE bucketing: picks go straight into per-src lists via atomics.
// ---------------------------------------------------------------------------
__global__ __launch_bounds__(256) void score_topk_kernel(const float* __restrict__ q) {
    __shared__ float ksh[Dd * NBb];    // 32 KB
    __shared__ float qsh[SBLK * Dd];   // 16 KB (reused for scores)

    const int h  = blockIdx.y;
    const int s0 = blockIdx.x * SBLK;
    const int tid = threadIdx.x;

    for (int i = tid; i < Dd * NBb; i += 256)
        ksh[i] = g_ksum_t[h * (Dd * NBb) + i];
    for (int i = tid; i < SBLK * Dd; i += 256) {
        int sl = i >> 7, d = i & (Dd - 1);
        qsh[i] = q[((size_t)(s0 + sl) * Hh + h) * Dd + d];
    }
    __syncthreads();

    const int ts = tid >> 4;
    const int tn = tid & 15;

    float acc[2][4];
#pragma unroll
    for (int i = 0; i < 2; ++i)
#pragma unroll
        for (int j = 0; j < 4; ++j) acc[i][j] = 0.f;

#pragma unroll 4
    for (int d = 0; d < Dd; ++d) {
        float k0 = ksh[d * NBb + tn];
        float k1 = ksh[d * NBb + tn + 16];
        float k2 = ksh[d * NBb + tn + 32];
        float k3 = ksh[d * NBb + tn + 48];
        float q0 = qsh[ts * Dd + d];
        float q1 = qsh[(ts + 16) * Dd + d];
        acc[0][0] += q0 * k0; acc[0][1] += q0 * k1;
        acc[0][2] += q0 * k2; acc[0][3] += q0 * k3;
        acc[1][0] += q1 * k0; acc[1][1] += q1 * k1;
        acc[1][2] += q1 * k2; acc[1][3] += q1 * k3;
    }
    __syncthreads();

    float* sc = qsh;   // scores [SBLK][65]
#pragma unroll
    for (int i = 0; i < 2; ++i)
#pragma unroll
        for (int j = 0; j < 4; ++j)
            sc[(ts + 16 * i) * 65 + (tn + 16 * j)] = acc[i][j];
    __syncthreads();

    if (tid < SBLK) {
        const float* row = sc + tid * 65;
        unsigned long long mask = 0ull;
        const int outbase = ((s0 + tid) * Hh + h) * KK;
#pragma unroll
        for (int p = 0; p < KK; ++p) {
            float bv = -3.402823466e38f;
            int bi = 0;
            for (int n = 0; n < NBb; ++n) {
                if ((mask >> n) & 1ull) continue;
                float v = row[n];
                if (v > bv) { bv = v; bi = n; }
            }
            mask |= 1ull << bi;
            // inline bucketing: pick id encodes (s,h,j); list order is
            // nondeterministic but each dest is written exactly once.
            int src = bi * Hh + h;
            int pos = atomicAdd(&g_cnt[src], 1);
            g_lists[src * CAPSRC + pos] = outbase + p;
        }
    }
}

// ---------------------------------------------------------------------------
// K3: split buckets into chunks of <= CHUNK dests for load balance
// ---------------------------------------------------------------------------
__global__ void chunk_kernel() {
    int src = blockIdx.x * 256 + threadIdx.x;
    if (src >= NSRC) return;
    int c = g_cnt[src];
    if (c == 0) return;
    int nch = (c + CHUNK - 1) / CHUNK;
    int base = atomicAdd(&g_nchunks, nch);
    for (int k = 0; k < nch; ++k)
        g_chunks[base + k] = make_int2(src, k * CHUNK);
}

// ---------------------------------------------------------------------------
// K4: gather. One CTA per chunk: load 16KB K + 16KB V src block into registers
// ONCE, replay to up to CHUNK destinations with streaming stores.
// ---------------------------------------------------------------------------
__global__ __launch_bounds__(256) void gather_kernel(const float* __restrict__ kc,
                                                     const float* __restrict__ vc,
                                                     float* __restrict__ out) {
    if ((int)blockIdx.x >= g_nchunks) return;
    int2 ch = g_chunks[blockIdx.x];
    const int src = ch.x;
    const int start = ch.y;
    const int cnt = g_cnt[src];
    const int end = min(start + CHUNK, cnt);

    const size_t blk4 = (size_t)(CBSs * Dd / 4);          // 1024 float4
    const float4* sk = (const float4*)kc + (size_t)src * blk4;
    const float4* sv = (const float4*)vc + (size_t)src * blk4;
    const int tid = threadIdx.x;

    float4 rk[4], rv[4];
#pragma unroll
    for (int i = 0; i < 4; ++i) {
        rk[i] = sk[tid + i * 256];
        rv[i] = sv[tid + i * 256];
    }

    for (int t = start; t < end; ++t) {
        int dest = g_lists[src * CAPSRC + t];
        float4* dk = (float4*)out + (size_t)dest * blk4;
        float4* dv = dk + (size_t)NPICK * blk4;
#pragma unroll
        for (int i = 0; i < 4; ++i) {
            __stcs(dk + tid + i * 256, rk[i]);
            __stcs(dv + tid + i * 256, rv[i]);
        }
    }
}

extern "C" void kernel_launch(void* const* d_in, const int* in_sizes, int n_in,
                              void* d_out, int out_size) {
    const float* q  = (const float*)d_in[0];
    const float* kc = (const float*)d_in[1];
    const float* vc = (const float*)d_in[2];
    float* out = (float*)d_out;

    ksum_kernel<<<NSRC, 128>>>(kc);
    score_topk_kernel<<<dim3(Ssz / SBLK, Hh), 256>>>(q);
    chunk_kernel<<<(NSRC + 255) / 256, 256>>>();
    gather_kernel<<<MAXCHUNKS, 256>>>(kc, vc, out);
}

// round 7
// speedup vs baseline: 1.0573x; 1.0269x over previous
#include <cuda_runtime.h>

#define Ssz  1024
#define Hh   16
#define Dd   128
#define NBb  64
#define CBSs 32
#define KK   4
#define SBLK 32

#define NPICK   (Ssz * Hh * KK)        // 65536
#define NSRC    (NBb * Hh)             // 1024
#define CAPSRC  1024                   // max picks per src: 4 picks per (s,h) are distinct n
#define SPLIT   4                      // fixed dest-split per src bucket

// scratch (no cudaMalloc allowed)
__device__ float g_ksum_t[Hh * Dd * NBb];     // [h][d][n]
__device__ int   g_cnt[NSRC];
__device__ int   g_lists[NSRC * CAPSRC];      // 4 MB

// ---------------------------------------------------------------------------
// K1: ksum[n,h,d] = sum_c kc[n,h,c,d] -> g_ksum_t[h][d][n], float4 loads.
// Also zeroes per-replay state (grid == NSRC, one counter per block).
// ---------------------------------------------------------------------------
__global__ __launch_bounds__(128) void ksum_kernel(const float* __restrict__ kc) {
    const int b   = blockIdx.x;          // n*H + h
    const int tid = threadIdx.x;         // 0..127
    if (tid == 0) g_cnt[b] = 0;

    const int d4 = tid & 31, g = tid >> 5;
    const float4* base = (const float4*)(kc + (size_t)b * (CBSs * Dd));
    float4 acc = make_float4(0.f, 0.f, 0.f, 0.f);
#pragma unroll
    for (int c = 0; c < 8; ++c) {
        float4 v = base[(size_t)(g * 8 + c) * 32 + d4];
        acc.x += v.x; acc.y += v.y; acc.z += v.z; acc.w += v.w;
    }

    __shared__ float4 sh[128];
    sh[tid] = acc;
    __syncthreads();

    if (tid < 32) {
        float4 a = sh[tid], p = sh[tid + 32], q2 = sh[tid + 64], r = sh[tid + 96];
        a.x += p.x + q2.x + r.x;
        a.y += p.y + q2.y + r.y;
        a.z += p.z + q2.z + r.z;
        a.w += p.w + q2.w + r.w;
        const int n = b >> 4, h = b & (Hh - 1);
        const int d0 = tid * 4;
        g_ksum_t[(h * Dd + d0 + 0) * NBb + n] = a.x;
        g_ksum_t[(h * Dd + d0 + 1) * NBb + n] = a.y;
        g_ksum_t[(h * Dd + d0 + 2) * NBb + n] = a.z;
        g_ksum_t[(h * Dd + d0 + 3) * NBb + n] = a.w;
    }
}

// ---------------------------------------------------------------------------
// K2: block scores + top-4 (jax.lax.top_k: strict >, lowest index wins ties)
// with INLINE bucketing: picks go straight into per-src lists via atomics.
// ---------------------------------------------------------------------------
__global__ __launch_bounds__(256) void score_topk_kernel(const float* __restrict__ q) {
    __shared__ float ksh[Dd * NBb];    // 32 KB
    __shared__ float qsh[SBLK * Dd];   // 16 KB (reused for scores)

    const int h  = blockIdx.y;
    const int s0 = blockIdx.x * SBLK;
    const int tid = threadIdx.x;

    for (int i = tid; i < Dd * NBb; i += 256)
        ksh[i] = g_ksum_t[h * (Dd * NBb) + i];
    for (int i = tid; i < SBLK * Dd; i += 256) {
        int sl = i >> 7, d = i & (Dd - 1);
        qsh[i] = q[((size_t)(s0 + sl) * Hh + h) * Dd + d];
    }
    __syncthreads();

    const int ts = tid >> 4;
    const int tn = tid & 15;

    float acc[2][4];
#pragma unroll
    for (int i = 0; i < 2; ++i)
#pragma unroll
        for (int j = 0; j < 4; ++j) acc[i][j] = 0.f;

#pragma unroll 4
    for (int d = 0; d < Dd; ++d) {
        float k0 = ksh[d * NBb + tn];
        float k1 = ksh[d * NBb + tn + 16];
        float k2 = ksh[d * NBb + tn + 32];
        float k3 = ksh[d * NBb + tn + 48];
        float q0 = qsh[ts * Dd + d];
        float q1 = qsh[(ts + 16) * Dd + d];
        acc[0][0] += q0 * k0; acc[0][1] += q0 * k1;
        acc[0][2] += q0 * k2; acc[0][3] += q0 * k3;
        acc[1][0] += q1 * k0; acc[1][1] += q1 * k1;
        acc[1][2] += q1 * k2; acc[1][3] += q1 * k3;
    }
    __syncthreads();

    float* sc = qsh;   // scores [SBLK][65]
#pragma unroll
    for (int i = 0; i < 2; ++i)
#pragma unroll
        for (int j = 0; j < 4; ++j)
            sc[(ts + 16 * i) * 65 + (tn + 16 * j)] = acc[i][j];
    __syncthreads();

    if (tid < SBLK) {
        const float* row = sc + tid * 65;
        unsigned long long mask = 0ull;
        const int outbase = ((s0 + tid) * Hh + h) * KK;
#pragma unroll
        for (int p = 0; p < KK; ++p) {
            float bv = -3.402823466e38f;
            int bi = 0;
            for (int n = 0; n < NBb; ++n) {
                if ((mask >> n) & 1ull) continue;
                float v = row[n];
                if (v > bv) { bv = v; bi = n; }
            }
            mask |= 1ull << bi;
            // inline bucketing: pick id encodes (s,h,j); list order is
            // nondeterministic but each dest is written exactly once.
            int src = bi * Hh + h;
            int pos = atomicAdd(&g_cnt[src], 1);
            g_lists[src * CAPSRC + pos] = outbase + p;
        }
    }
}

// ---------------------------------------------------------------------------
// K3: gather with fixed 4-way bucket split. CTA b: src = b>>2, slot = b&3,
// serves dests t = slot, slot+4, ... Load 16KB K + 16KB V src block into
// registers ONCE, replay to its dests with streaming stores.
// ---------------------------------------------------------------------------
__global__ __launch_bounds__(256) void gather_kernel(const float* __restrict__ kc,
                                                     const float* __restrict__ vc,
                                                     float* __restrict__ out) {
    const int b    = blockIdx.x;
    const int src  = b >> 2;
    const int slot = b & (SPLIT - 1);
    const int cnt  = g_cnt[src];
    if (slot >= cnt) return;

    const size_t blk4 = (size_t)(CBSs * Dd / 4);          // 1024 float4
    const float4* sk = (const float4*)kc + (size_t)src * blk4;
    const float4* sv = (const float4*)vc + (size_t)src * blk4;
    const int tid = threadIdx.x;

    float4 rk[4], rv[4];
#pragma unroll
    for (int i = 0; i < 4; ++i) {
        rk[i] = sk[tid + i * 256];
        rv[i] = sv[tid + i * 256];
    }

    const int* lst = g_lists + src * CAPSRC;
    for (int t = slot; t < cnt; t += SPLIT) {
        int dest = __ldg(lst + t);
        float4* dk = (float4*)out + (size_t)dest * blk4;
        float4* dv = dk + (size_t)NPICK * blk4;
#pragma unroll
        for (int i = 0; i < 4; ++i) {
            __stcs(dk + tid + i * 256, rk[i]);
            __stcs(dv + tid + i * 256, rv[i]);
        }
    }
}

extern "C" void kernel_launch(void* const* d_in, const int* in_sizes, int n_in,
                              void* d_out, int out_size) {
    const float* q  = (const float*)d_in[0];
    const float* kc = (const float*)d_in[1];
    const float* vc = (const float*)d_in[2];
    float* out = (float*)d_out;

    ksum_kernel<<<NSRC, 128>>>(kc);
    score_topk_kernel<<<dim3(Ssz / SBLK, Hh), 256>>>(q);
    gather_kernel<<<NSRC * SPLIT, 256>>>(kc, vc, out);
}

// round 11
// speedup vs baseline: 1.0914x; 1.0322x over previous
#include <cuda_runtime.h>

#define Ssz  1024
#define Hh   16
#define Dd   128
#define NBb  64
#define CBSs 32
#define KK   4
#define SBLK 32

#define NPICK   (Ssz * Hh * KK)        // 65536
#define NSRC    (NBb * Hh)             // 1024
#define CAPSRC  1024                   // max picks per src (<= #s)
#define SPLIT   4                      // fixed dest-split per src bucket

#define NEG_INF __int_as_float(0xff800000)

// scratch (no cudaMalloc allowed)
__device__ float g_ksum_t[Hh * Dd * NBb];     // [h][d][n]
__device__ int   g_cnt[NSRC];
__device__ int   g_lists[NSRC * CAPSRC];      // 4 MB

// ---------------------------------------------------------------------------
// K1: ksum[n,h,d] = sum_c kc[n,h,c,d] -> g_ksum_t[h][d][n], float4 loads.
// Also zeroes per-replay counters (grid == NSRC).
// ---------------------------------------------------------------------------
__global__ __launch_bounds__(128) void ksum_kernel(const float* __restrict__ kc) {
    const int b   = blockIdx.x;          // n*H + h
    const int tid = threadIdx.x;
    if (tid == 0) g_cnt[b] = 0;

    const int d4 = tid & 31, g = tid >> 5;
    const float4* base = (const float4*)(kc + (size_t)b * (CBSs * Dd));
    float4 acc = make_float4(0.f, 0.f, 0.f, 0.f);
#pragma unroll
    for (int c = 0; c < 8; ++c) {
        float4 v = base[(size_t)(g * 8 + c) * 32 + d4];
        acc.x += v.x; acc.y += v.y; acc.z += v.z; acc.w += v.w;
    }

    __shared__ float4 sh[128];
    sh[tid] = acc;
    __syncthreads();

    if (tid < 32) {
        float4 a = sh[tid], p = sh[tid + 32], q2 = sh[tid + 64], r = sh[tid + 96];
        a.x += p.x + q2.x + r.x;
        a.y += p.y + q2.y + r.y;
        a.z += p.z + q2.z + r.z;
        a.w += p.w + q2.w + r.w;
        const int n = b >> 4, h = b & (Hh - 1);
        const int d0 = tid * 4;
        g_ksum_t[(h * Dd + d0 + 0) * NBb + n] = a.x;
        g_ksum_t[(h * Dd + d0 + 1) * NBb + n] = a.y;
        g_ksum_t[(h * Dd + d0 + 2) * NBb + n] = a.z;
        g_ksum_t[(h * Dd + d0 + 3) * NBb + n] = a.w;
    }
}

// ---------------------------------------------------------------------------
// K2: block scores + top-4 (jax.lax.top_k: strict >, lowest index wins ties)
// with inline bucketing. Inner loop: 1 LDS.128 (4 consecutive n) + 2 scalar
// q broadcasts per 8 FFMA. Top-k: one warp per s-row, butterfly argmax.
// ---------------------------------------------------------------------------
__global__ __launch_bounds__(256) void score_topk_kernel(const float* __restrict__ q) {
    __shared__ float ksh[Dd * NBb];    // 32 KB, [d][n]
    __shared__ float qsh[SBLK * Dd];   // 16 KB (reused for scores [32][65])

    const int h  = blockIdx.y;
    const int s0 = blockIdx.x * SBLK;
    const int tid = threadIdx.x;

    // float4 staging
    {
        const float4* gk4 = (const float4*)(g_ksum_t + h * (Dd * NBb));
        float4* k4 = (float4*)ksh;
#pragma unroll
        for (int i = 0; i < 8; ++i)
            k4[tid + i * 256] = gk4[tid + i * 256];
        const float4* gq4 = (const float4*)q;
        float4* q4 = (float4*)qsh;
#pragma unroll
        for (int i = 0; i < 4; ++i) {
            int idx = tid + i * 256;                 // sl*32 + d4
            int sl = idx >> 5, d4 = idx & 31;
            q4[idx] = gq4[((size_t)(s0 + sl) * Hh + h) * 32 + d4];
        }
    }
    __syncthreads();

    const int ts = tid >> 4;        // s rows {ts, ts+16}
    const int tn = tid & 15;        // n cols {4tn..4tn+3}

    float acc[2][4];
#pragma unroll
    for (int i = 0; i < 2; ++i)
#pragma unroll
        for (int j = 0; j < 4; ++j) acc[i][j] = 0.f;

    const float4* k4 = (const float4*)ksh;
#pragma unroll 4
    for (int d = 0; d < Dd; ++d) {
        float4 kv = k4[d * 16 + tn];
        float q0 = qsh[ts * Dd + d];
        float q1 = qsh[(ts + 16) * Dd + d];
        acc[0][0] += q0 * kv.x; acc[0][1] += q0 * kv.y;
        acc[0][2] += q0 * kv.z; acc[0][3] += q0 * kv.w;
        acc[1][0] += q1 * kv.x; acc[1][1] += q1 * kv.y;
        acc[1][2] += q1 * kv.z; acc[1][3] += q1 * kv.w;
    }
    __syncthreads();

    float* sc = qsh;   // scores [SBLK][65] padded
#pragma unroll
    for (int i = 0; i < 2; ++i)
#pragma unroll
        for (int j = 0; j < 4; ++j)
            sc[(ts + 16 * i) * 65 + (tn * 4 + j)] = acc[i][j];
    __syncthreads();

    // top-4 per row: warp w handles rows w*4 .. w*4+3
    const int w = tid >> 5, l = tid & 31;
#pragma unroll
    for (int rr = 0; rr < 4; ++rr) {
        const int r = w * 4 + rr;
        float va = sc[r * 65 + l];
        float vb = sc[r * 65 + l + 32];
        const int outbase = ((s0 + r) * Hh + h) * KK;
#pragma unroll
        for (int p = 0; p < KK; ++p) {
            float v;  int idx;
            if (vb > va) { v = vb; idx = l + 32; }
            else         { v = va; idx = l; }
#pragma unroll
            for (int off = 16; off; off >>= 1) {
                float vo = __shfl_xor_sync(0xffffffffu, v, off);
                int   io = __shfl_xor_sync(0xffffffffu, idx, off);
                if (vo > v || (vo == v && io < idx)) { v = vo; idx = io; }
            }
            // all lanes agree on (v, idx); exclude and emit
            if (idx == l)      va = NEG_INF;
            if (idx == l + 32) vb = NEG_INF;
            if (l == 0) {
                int src = idx * Hh + h;
                int pos = atomicAdd(&g_cnt[src], 1);
                g_lists[src * CAPSRC + pos] = outbase + p;
            }
        }
    }
}

// ---------------------------------------------------------------------------
// K3: gather with fixed 4-way bucket split. CTA b: src = b>>2, slot = b&3.
// Load 16KB K + 16KB V src block into registers ONCE, replay with streaming
// stores.
// ---------------------------------------------------------------------------
__global__ __launch_bounds__(256) void gather_kernel(const float* __restrict__ kc,
                                                     const float* __restrict__ vc,
                                                     float* __restrict__ out) {
    const int b    = blockIdx.x;
    const int src  = b >> 2;
    const int slot = b & (SPLIT - 1);
    const int cnt  = g_cnt[src];
    if (slot >= cnt) return;

    const size_t blk4 = (size_t)(CBSs * Dd / 4);          // 1024 float4
    const float4* sk = (const float4*)kc + (size_t)src * blk4;
    const float4* sv = (const float4*)vc + (size_t)src * blk4;
    const int tid = threadIdx.x;

    float4 rk[4], rv[4];
#pragma unroll
    for (int i = 0; i < 4; ++i) {
        rk[i] = sk[tid + i * 256];
        rv[i] = sv[tid + i * 256];
    }

    const int* lst = g_lists + src * CAPSRC;
    for (int t = slot; t < cnt; t += SPLIT) {
        int dest = __ldg(lst + t);
        float4* dk = (float4*)out + (size_t)dest * blk4;
        float4* dv = dk + (size_t)NPICK * blk4;
#pragma unroll
        for (int i = 0; i < 4; ++i) {
            __stcs(dk + tid + i * 256, rk[i]);
            __stcs(dv + tid + i * 256, rv[i]);
        }
    }
}

extern "C" void kernel_launch(void* const* d_in, const int* in_sizes, int n_in,
                              void* d_out, int out_size) {
    const float* q  = (const float*)d_in[0];
    const float* kc = (const float*)d_in[1];
    const float* vc = (const float*)d_in[2];
    float* out = (float*)d_out;

    ksum_kernel<<<NSRC, 128>>>(kc);
    score_topk_kernel<<<dim3(Ssz / SBLK, Hh), 256>>>(q);
    gather_kernel<<<NSRC * SPLIT, 256>>>(kc, vc, out);
}